// round 15
// baseline (speedup 1.0000x reference)
#include <cuda_runtime.h>
#include <cuda_bf16.h>
#include <cuda_fp16.h>
#include <math.h>
#include <stdint.h>

#define B_DIM 2048
#define N_IN  512
#define N_OUT 512
#define RSQRT2 0.70710678118654752440f
#define NSLT  52             // total K-slices across all 8 output blades
#define NKT_XR 8             // xr GEMM: single fp16 pass, 8 k-tiles of 64
#define BN    ((size_t)B_DIM * N_IN)

// ---------------- device scratch (static globals; no runtime alloc) --------
__device__ __half g_A[(size_t)NSLT * 512 * B_DIM];                // 109 MB (fp16)
__device__ __half g_B[(size_t)NSLT * 512 * N_OUT];                // 27.3 MB (fp16)
__device__ float g_outT[(size_t)8 * B_DIM * N_OUT];               // 33.5 MB (xr planes, then out planes)
__device__ __half g_xf[(size_t)8 * BN];                           // 8.4 MB (fp16)
__device__ __half g_wrf[(size_t)4 * N_IN * N_IN];                 // 2.1 MB (fp16)

// ---- Cl(3,0) tables: blades 0:1 1:e1 2:e2 3:e3 4:e12 5:e13 6:e23 7:e123 --
__device__ constexpr int c_G[8]  = {0,1,1,1,2,2,2,3};
__device__ constexpr int c_MS[8] = {0,1,2,4,3,5,6,7};   // blade idx <-> bitmask (involution)

// ---- per-bj path-grouped slice tables (derived from Cayley c_P/c_SG) ------
// slices per bj (incl. final left-linear slice), and cumulative offsets
__device__ constexpr int c_NSL[8] = {5,7,7,7,7,7,7,5};
__device__ constexpr int c_OFF[8] = {0,5,12,19,26,33,40,47};
// per slice: weight path (-1 => left-linear slice), #A-terms, t-indices, signs
__device__ constexpr int c_SPATH[NSLT] = {
    0,4,10,16,-1,
    1,5,6,11,12,17,-1,
    1,5,6,11,12,17,-1,
    1,5,6,11,12,17,-1,
    2,7,8,13,14,18,-1,
    2,7,8,13,14,18,-1,
    2,7,8,13,14,18,-1,
    3,9,15,19,-1};
__device__ constexpr int c_SNT[NSLT] = {
    1,3,3,1,0,
    1,1,2,2,1,1,0,
    1,1,2,2,1,1,0,
    1,1,2,2,1,1,0,
    1,2,1,1,2,1,0,
    1,2,1,1,2,1,0,
    1,2,1,1,2,1,0,
    1,3,3,1,0};
__device__ constexpr int c_ST[NSLT][3] = {
    {0,0,0},{1,2,3},{4,5,6},{7,0,0},{0,0,0},
    {0,0,0},{1,0,0},{2,3,0},{4,5,0},{6,0,0},{7,0,0},{0,0,0},
    {0,0,0},{2,0,0},{1,3,0},{4,6,0},{5,0,0},{7,0,0},{0,0,0},
    {0,0,0},{3,0,0},{1,2,0},{5,6,0},{4,0,0},{7,0,0},{0,0,0},
    {0,0,0},{1,2,0},{3,0,0},{4,0,0},{5,6,0},{7,0,0},{0,0,0},
    {0,0,0},{1,3,0},{2,0,0},{5,0,0},{4,6,0},{7,0,0},{0,0,0},
    {0,0,0},{2,3,0},{1,0,0},{6,0,0},{4,5,0},{7,0,0},{0,0,0},
    {0,0,0},{1,2,3},{4,5,6},{7,0,0},{0,0,0}};
__device__ constexpr int c_SSG[NSLT][3] = {   // 1 = +, 0 = -
    {1,1,1},{1,1,1},{0,0,0},{0,1,1},{1,1,1},
    {1,1,1},{1,1,1},{0,0,1},{1,1,1},{0,1,1},{0,1,1},{1,1,1},
    {1,1,1},{1,1,1},{1,0,1},{0,1,1},{1,1,1},{1,1,1},{1,1,1},
    {1,1,1},{1,1,1},{1,1,1},{0,0,1},{0,1,1},{0,1,1},{1,1,1},
    {1,1,1},{1,0,1},{1,1,1},{1,1,1},{0,1,1},{1,1,1},{1,1,1},
    {1,1,1},{1,0,1},{0,1,1},{1,1,1},{1,0,1},{0,1,1},{1,1,1},
    {1,1,1},{1,0,1},{1,1,1},{1,1,1},{0,1,1},{1,1,1},{1,1,1},
    {1,1,1},{1,0,1},{1,0,1},{1,1,1},{1,1,1}};

// ---------------- helpers ---------------------------------------------------
__device__ __forceinline__ uint32_t smem_u32(const void* p) {
    uint32_t a;
    asm("{ .reg .u64 t; cvta.to.shared.u64 t, %1; cvt.u32.u64 %0, t; }" : "=r"(a) : "l"(p));
    return a;
}
#define SWZ(o) ((o) ^ (((o) >> 3) & 0x70))

__device__ __forceinline__ void ldm4(uint32_t* r, uint32_t addr) {
    asm volatile("ldmatrix.sync.aligned.m8n8.x4.shared.b16 {%0,%1,%2,%3}, [%4];"
        : "=r"(r[0]), "=r"(r[1]), "=r"(r[2]), "=r"(r[3]) : "r"(addr));
}
__device__ __forceinline__ void mma_f16(float* c, const uint32_t* a, uint32_t b0, uint32_t b1) {
    asm volatile(
        "mma.sync.aligned.m16n8k16.row.col.f32.f16.f16.f32 "
        "{%0,%1,%2,%3}, {%4,%5,%6,%7}, {%8,%9}, {%0,%1,%2,%3};"
        : "+f"(c[0]), "+f"(c[1]), "+f"(c[2]), "+f"(c[3])
        : "r"(a[0]), "r"(a[1]), "r"(a[2]), "r"(a[3]), "r"(b0), "r"(b1));
}
__device__ __forceinline__ void cp16(uint32_t d, const void* g) {
    asm volatile("cp.async.cg.shared.global [%0], [%1], 16;" :: "r"(d), "l"(g));
}
#define CP_COMMIT() asm volatile("cp.async.commit_group;")
#define CP_WAIT1()  asm volatile("cp.async.wait_group 1;")
#define CP_WAIT0()  asm volatile("cp.async.wait_group 0;")

// ============================================================================
// splitX: x[b,n,8] -> g_xf planes [i][b][n] (fp16)
// ============================================================================
__global__ __launch_bounds__(256)
void k_splitX(const float* __restrict__ x)
{
    size_t idx = blockIdx.x * 256 + threadIdx.x;    // (b,n)
    float x8[8];
    *(float4*)(x8)     = *(const float4*)(x + idx * 8);
    *(float4*)(x8 + 4) = *(const float4*)(x + idx * 8 + 4);
#pragma unroll
    for (int i = 0; i < 8; ++i)
        g_xf[(size_t)i * BN + idx] = __float2half(x8[i]);
}

// ============================================================================
// prepW (fused splitW + buildB), 2 n's per thread, half2 stores.
//   g_wrf[g][m][n] = fp16(w_right[m,n,g])
//   g_B slices (path-grouped, signs live in A now):
//     slice s of bj: path>=0 -> weight[m,n,path]; left -> w_left[m,n,G[bj]]
// ============================================================================
__global__ __launch_bounds__(256)
void k_prepW(const float* __restrict__ weight, const float* __restrict__ w_left,
             const float* __restrict__ w_right)
{
    size_t idx2 = blockIdx.x * 256 + threadIdx.x;   // (m, n2)
    int m = (int)(idx2 >> 8), n = (int)(idx2 & 255) * 2;
    size_t bn0 = (size_t)m * 512 + n;
    float w[2][20], wl[2][4], wr[2][4];
#pragma unroll
    for (int j = 0; j < 2; ++j) {
#pragma unroll
        for (int q = 0; q < 5; ++q)
            *(float4*)(w[j] + q * 4) = *(const float4*)(weight + (bn0 + j) * 20 + q * 4);
        *(float4*)(wl[j]) = *(const float4*)(w_left + (bn0 + j) * 4);
        *(float4*)(wr[j]) = *(const float4*)(w_right + (bn0 + j) * 4);
    }

#pragma unroll
    for (int g = 0; g < 4; ++g)
        *(__half2*)(g_wrf + (size_t)g * N_IN * N_IN + bn0) =
            __floats2half2_rn(wr[0][g], wr[1][g]);

#pragma unroll
    for (int bj = 0; bj < 8; ++bj) {
        const int nsl = c_NSL[bj];
        size_t base = (size_t)c_OFF[bj] * 512 * N_OUT + (size_t)m * (nsl * 512) + n;
#pragma unroll
        for (int s = 0; s < 7; ++s) {
            if (s >= nsl) break;
            const int si = c_OFF[bj] + s;
            const int p = c_SPATH[si];
            float v0, v1;
            if (p >= 0) { v0 = w[0][p]; v1 = w[1][p]; }
            else        { v0 = wl[0][c_G[bj]]; v1 = wl[1][c_G[bj]]; }
            *(__half2*)(g_B + base + (size_t)s * 512) = __floats2half2_rn(v0, v1);
        }
    }
}

// ============================================================================
// Shared GEMM core: 128 x 128 CTA tile, 4 warps of 64x64, BK=64,
// 3-stage cp.async pipeline, single __syncthreads per k-iter, 128 threads.
// smem: 3 stages x (A 16KB + B 16KB) = 96KB dynamic.
// ============================================================================
struct GemmCtx {
    uint32_t smb;
    int lane, warp_m, warp_n;
    int ldrow, ldc16;
    uint32_t ld_sw;
    uint32_t a_lin, a_sw, a_kl;
    uint32_t b_lin, b_sw, b_kl;
    __device__ __forceinline__ void init(int tid) {
        lane = tid & 31;
        int wid = tid >> 5;
        warp_m = wid >> 1; warp_n = wid & 1;
        ldrow = tid >> 3; ldc16 = tid & 7;
        ld_sw = SWZ((uint32_t)(ldrow * 128 + ldc16 * 16));
        int a_r = warp_m * 64 + (lane & 7) + ((lane >> 3) & 1) * 8;
        a_lin = a_r * 128; a_sw = (a_r & 7) << 4; a_kl = (lane >> 4) * 16;
        int b_r = warp_n * 64 + (lane & 7) + (lane >> 4) * 8;
        b_lin = b_r * 128; b_sw = (b_r & 7) << 4; b_kl = ((lane >> 3) & 1) * 16;
    }
};

__device__ __forceinline__ void gemm_load(const GemmCtx& g, int s,
                                          const __half* Ap, size_t a_row0,
                                          const __half* Bp, size_t b_row0,
                                          size_t ldk, int kk) {
    const uint32_t sA = g.smb + (uint32_t)s * 32768u;
    const uint32_t sB = sA + 16384u;
#pragma unroll
    for (int j = 0; j < 8; ++j) {
        int row = g.ldrow + j * 16;
        cp16(sA + g.ld_sw + j * 2048u, Ap + a_row0 + (size_t)row * ldk + kk * 64 + g.ldc16 * 8);
        cp16(sB + g.ld_sw + j * 2048u, Bp + b_row0 + (size_t)row * ldk + kk * 64 + g.ldc16 * 8);
    }
    CP_COMMIT();
}

__device__ __forceinline__ void gemm_compute(const GemmCtx& g, int s, float c[4][8][4]) {
    const uint32_t sA = g.smb + (uint32_t)s * 32768u;
    const uint32_t sB = sA + 16384u;
#pragma unroll
    for (int k16 = 0; k16 < 4; ++k16) {
        uint32_t af[4][4], bf[4][4];
#pragma unroll
        for (int mi = 0; mi < 4; ++mi)
            ldm4(af[mi], sA + g.a_lin + mi * 2048u + ((k16 * 32u + g.a_kl) ^ g.a_sw));
#pragma unroll
        for (int nj = 0; nj < 4; ++nj)
            ldm4(bf[nj], sB + g.b_lin + nj * 2048u + ((k16 * 32u + g.b_kl) ^ g.b_sw));
#pragma unroll
        for (int mi = 0; mi < 4; ++mi)
#pragma unroll
            for (int nj = 0; nj < 4; ++nj) {
                mma_f16(c[mi][nj * 2 + 0], af[mi], bf[nj][0], bf[nj][1]);
                mma_f16(c[mi][nj * 2 + 1], af[mi], bf[nj][2], bf[nj][3]);
            }
    }
}

__device__ __forceinline__ void gemm_store(const GemmCtx& g, float c[4][8][4],
                                           float* base, int b0, int n0, int ldn) {
    const int mrow = b0 + g.warp_m * 64 + (g.lane >> 2);
    const int ncol = n0 + g.warp_n * 64 + (g.lane & 3) * 2;
#pragma unroll
    for (int mi = 0; mi < 4; ++mi)
#pragma unroll
        for (int n8 = 0; n8 < 8; ++n8) {
            float* p0 = base + (size_t)(mrow + mi * 16) * ldn + ncol + n8 * 8;
            float* p1 = base + (size_t)(mrow + mi * 16 + 8) * ldn + ncol + n8 * 8;
            *(float2*)p0 = make_float2(c[mi][n8][0], c[mi][n8][1]);
            *(float2*)p1 = make_float2(c[mi][n8][2], c[mi][n8][3]);
        }
}

// ============================================================================
// xr GEMM (tensor, single fp16): g_outT[i][b][m] = sum_n x[b,n,i]*w_right[m,n,G[i]]
// grid (4, 16, 8), 128 threads.
// ============================================================================
__global__ __launch_bounds__(128)
void k_gemm_xr()
{
    extern __shared__ char sm[];
    GemmCtx g; g.smb = smem_u32(sm); g.init(threadIdx.x);
    const int n0 = blockIdx.x * 128, b0 = blockIdx.y * 128;
    const int ib = blockIdx.z, gg = c_G[ib];

    const size_t a_row0 = ((size_t)ib * B_DIM + b0) * N_IN;
    const size_t b_row0 = ((size_t)gg * N_IN + n0) * N_IN;

    float c[4][8][4];
#pragma unroll
    for (int mi = 0; mi < 4; ++mi)
#pragma unroll
        for (int nn = 0; nn < 8; ++nn)
#pragma unroll
            for (int q = 0; q < 4; ++q) c[mi][nn][q] = 0.f;

    gemm_load(g, 0, g_xf, a_row0, g_wrf, b_row0, (size_t)N_IN, 0);
    gemm_load(g, 1, g_xf, a_row0, g_wrf, b_row0, (size_t)N_IN, 1);
#pragma unroll 1
    for (int kt = 0; kt < NKT_XR; ++kt) {
        if (kt + 1 < NKT_XR) CP_WAIT1(); else CP_WAIT0();
        __syncthreads();
        if (kt + 2 < NKT_XR)
            gemm_load(g, (kt + 2) % 3, g_xf, a_row0, g_wrf, b_row0, (size_t)N_IN, kt + 2);
        gemm_compute(g, kt % 3, c);
    }

    gemm_store(g, c, g_outT + (size_t)ib * B_DIM * N_IN, b0, n0, N_IN);
}

// ============================================================================
// buildA fused with normalization, path-grouped slices, 2 n's per thread:
//   read raw xr planes g_outT[i][b][n], normalize, combine with fp16 x planes,
//   pre-sum path groups in fp32, emit A (fp16) in the 52-slice layout.
// ============================================================================
__global__ __launch_bounds__(256)
void k_buildA(const float* __restrict__ norm_a)
{
    size_t idx2 = blockIdx.x * 256 + threadIdx.x;   // (b, n2)
    int b = (int)(idx2 >> 8), n = (int)(idx2 & 255) * 2;
    size_t bn0 = (size_t)b * 512 + n;

    float r8[2][8];
#pragma unroll
    for (int i = 0; i < 8; ++i) {
        float2 v = *(const float2*)(g_outT + (size_t)i * BN + bn0);
        r8[0][i] = v.x; r8[1][i] = v.y;
    }

#pragma unroll
    for (int j = 0; j < 2; ++j) {
        float* r = r8[j];
        float n0 = fabsf(r[0]);
        float n1 = sqrtf(r[1]*r[1] + r[2]*r[2] + r[3]*r[3]);
        float n2 = sqrtf(r[4]*r[4] + r[5]*r[5] + r[6]*r[6]);
        float n3 = fabsf(r[7]);
        float4 na = *(const float4*)(norm_a + (n + j) * 4);
        float s0 = 1.f / (1.f + expf(-na.x));
        float s1 = 1.f / (1.f + expf(-na.y));
        float s2 = 1.f / (1.f + expf(-na.z));
        float s3 = 1.f / (1.f + expf(-na.w));
        float d0 = 1.f / (s0 * (n0 - 1.f) + 1.f + 1e-6f);
        float d1 = 1.f / (s1 * (n1 - 1.f) + 1.f + 1e-6f);
        float d2 = 1.f / (s2 * (n2 - 1.f) + 1.f + 1e-6f);
        float d3 = 1.f / (s3 * (n3 - 1.f) + 1.f + 1e-6f);
        r[0] *= d0; r[1] *= d1; r[2] *= d1; r[3] *= d1;
        r[4] *= d2; r[5] *= d2; r[6] *= d2; r[7] *= d3;
    }

    float x8[2][8];
#pragma unroll
    for (int i = 0; i < 8; ++i) {
        __half2 xv = *(const __half2*)(g_xf + (size_t)i * BN + bn0);
        float2 xf = __half22float2(xv);
        x8[0][i] = xf.x; x8[1][i] = xf.y;
    }

#pragma unroll
    for (int bj = 0; bj < 8; ++bj) {
        const int nsl = c_NSL[bj];
        size_t base = (size_t)c_OFF[bj] * 512 * B_DIM + (size_t)b * (nsl * 512) + n;
#pragma unroll
        for (int s = 0; s < 7; ++s) {
            if (s >= nsl) break;
            const int si = c_OFF[bj] + s;
            const int nt = c_SNT[si];
            float v0, v1;
            if (nt == 0) {              // left-linear slice
                v0 = x8[0][bj]; v1 = x8[1][bj];
            } else {
                v0 = 0.f; v1 = 0.f;
#pragma unroll
                for (int q = 0; q < 3; ++q) {
                    if (q >= nt) break;
                    const int t = c_ST[si][q];
                    const int bk = c_MS[c_MS[t] ^ c_MS[bj]];
                    if (c_SSG[si][q]) {
                        v0 += x8[0][t] * r8[0][bk];
                        v1 += x8[1][t] * r8[1][bk];
                    } else {
                        v0 -= x8[0][t] * r8[0][bk];
                        v1 -= x8[1][t] * r8[1][bk];
                    }
                }
            }
            *(__half2*)(g_A + base + (size_t)s * 512) = __floats2half2_rn(v0, v1);
        }
    }
}

// ============================================================================
// main GEMM (tensor, fp16, path-grouped K): g_outT[bj][b][m] = sum_k A[b,k]*B[m,k]
// grid (4, 16, 8), 128 threads. K per bj = c_NSL[bj]*512 (NKT = c_NSL*8).
// ============================================================================
__global__ __launch_bounds__(128)
void k_gemm()
{
    extern __shared__ char sm[];
    GemmCtx g; g.smb = smem_u32(sm); g.init(threadIdx.x);
    const int n0 = blockIdx.x * 128, b0 = blockIdx.y * 128;
    const int bj = blockIdx.z;

    const int nsl = c_NSL[bj];
    const size_t ldk = (size_t)nsl * 512;
    const int nkt = nsl * 8;
    const size_t a_row0 = (size_t)c_OFF[bj] * 512 * B_DIM + (size_t)b0 * ldk;
    const size_t b_row0 = (size_t)c_OFF[bj] * 512 * N_OUT + (size_t)n0 * ldk;

    float c[4][8][4];
#pragma unroll
    for (int mi = 0; mi < 4; ++mi)
#pragma unroll
        for (int nn = 0; nn < 8; ++nn)
#pragma unroll
            for (int q = 0; q < 4; ++q) c[mi][nn][q] = 0.f;

    gemm_load(g, 0, g_A, a_row0, g_B, b_row0, ldk, 0);
    gemm_load(g, 1, g_A, a_row0, g_B, b_row0, ldk, 1);
#pragma unroll 1
    for (int kt = 0; kt < nkt; ++kt) {
        if (kt + 1 < nkt) CP_WAIT1(); else CP_WAIT0();
        __syncthreads();
        if (kt + 2 < nkt)
            gemm_load(g, (kt + 2) % 3, g_A, a_row0, g_B, b_row0, ldk, kt + 2);
        gemm_compute(g, kt % 3, c);
    }

    gemm_store(g, c, g_outT + (size_t)bj * B_DIM * N_OUT, b0, n0, N_OUT);
}

// ============================================================================
// merge: out[b][m][bj] = (g_outT[bj][b][m] + (bj==0)*b_left[m]) * RSQRT2
// ============================================================================
__global__ __launch_bounds__(256)
void k_merge(const float* __restrict__ b_left, float* __restrict__ out)
{
    size_t idx = blockIdx.x * 256 + threadIdx.x;
    int m = (int)(idx & 511);
    float v[8];
#pragma unroll
    for (int bj = 0; bj < 8; ++bj)
        v[bj] = g_outT[(size_t)bj * B_DIM * N_OUT + idx];
    v[0] += b_left[m];
    float* dst = out + idx * 8;
    *(float4*)(dst)     = make_float4(v[0]*RSQRT2, v[1]*RSQRT2, v[2]*RSQRT2, v[3]*RSQRT2);
    *(float4*)(dst + 4) = make_float4(v[4]*RSQRT2, v[5]*RSQRT2, v[6]*RSQRT2, v[7]*RSQRT2);
}

// ============================================================================
extern "C" void kernel_launch(void* const* d_in, const int* in_sizes, int n_in,
                              void* d_out, int out_size) {
    const float* x       = (const float*)d_in[0];
    const float* weight  = (const float*)d_in[1];
    const float* w_right = (const float*)d_in[2];
    const float* w_left  = (const float*)d_in[3];
    const float* b_left  = (const float*)d_in[4];
    const float* norm_a  = (const float*)d_in[5];
    float* out = (float*)d_out;

    cudaFuncSetAttribute(k_gemm,    cudaFuncAttributeMaxDynamicSharedMemorySize, 98304);
    cudaFuncSetAttribute(k_gemm_xr, cudaFuncAttributeMaxDynamicSharedMemorySize, 98304);

    k_splitX<<<(int)(BN / 256), 256>>>(x);
    k_prepW<<<(N_OUT * N_IN / 2) / 256, 256>>>(weight, w_left, w_right);
    dim3 gx(N_IN / 128, B_DIM / 128, 8);
    k_gemm_xr<<<gx, 128, 98304>>>();
    k_buildA<<<(int)(BN / 2 / 256), 256>>>(norm_a);
    dim3 gg(N_OUT / 128, B_DIM / 128, 8);
    k_gemm<<<gg, 128, 98304>>>();
    k_merge<<<(B_DIM * N_OUT) / 256, 256>>>(b_left, out);
}

// round 16
// speedup vs baseline: 1.4318x; 1.4318x over previous
#include <cuda_runtime.h>
#include <cuda_bf16.h>
#include <cuda_fp16.h>
#include <math.h>
#include <stdint.h>

#define B_DIM 2048
#define N_IN  512
#define N_OUT 512
#define RSQRT2 0.70710678118654752440f
#define NSL   7              // uniform K-slices per output blade (padded)
#define KU    (NSL * 512)    // 3584, compile-time K of main GEMM
#define NKT   (NSL * 8)      // 56 k-tiles of 64
#define NKT_XR 8             // xr GEMM: single fp16 pass, 8 k-tiles of 64
#define BN    ((size_t)B_DIM * N_IN)

// ---------------- device scratch (static globals; no runtime alloc) --------
__device__ __half g_A[(size_t)8 * B_DIM * KU];                    // 117 MB (fp16)
__device__ __half g_B[(size_t)8 * N_OUT * KU];                    // 29.4 MB (fp16)
__device__ float g_outT[(size_t)8 * B_DIM * N_OUT];               // 33.5 MB (xr planes, then out planes)
__device__ __half g_xf[(size_t)8 * BN];                           // 8.4 MB (fp16)
__device__ __half g_wrf[(size_t)4 * N_IN * N_IN];                 // 2.1 MB (fp16)

// ---- Cl(3,0) tables: blades 0:1 1:e1 2:e2 3:e3 4:e12 5:e13 6:e23 7:e123 --
__device__ constexpr int c_G[8]  = {0,1,1,1,2,2,2,3};
__device__ constexpr int c_MS[8] = {0,1,2,4,3,5,6,7};   // blade idx <-> bitmask (involution)

// ---- uniform per-bj path-grouped slice tables (7 slices each, padded) -----
// c_SPATH: weight path; -1 = left-linear slice; -2 = zero padding slice
// c_SNT:   #bilinear terms; 0 = left; -1 = zero pad
__device__ constexpr int c_SPATH[56] = {
     0, 4,10,16,-1,-2,-2,
     1, 5, 6,11,12,17,-1,
     1, 5, 6,11,12,17,-1,
     1, 5, 6,11,12,17,-1,
     2, 7, 8,13,14,18,-1,
     2, 7, 8,13,14,18,-1,
     2, 7, 8,13,14,18,-1,
     3, 9,15,19,-1,-2,-2};
__device__ constexpr int c_SNT[56] = {
     1, 3, 3, 1, 0,-1,-1,
     1, 1, 2, 2, 1, 1, 0,
     1, 1, 2, 2, 1, 1, 0,
     1, 1, 2, 2, 1, 1, 0,
     1, 2, 1, 1, 2, 1, 0,
     1, 2, 1, 1, 2, 1, 0,
     1, 2, 1, 1, 2, 1, 0,
     1, 3, 3, 1, 0,-1,-1};
__device__ constexpr int c_ST[56][3] = {
    {0,0,0},{1,2,3},{4,5,6},{7,0,0},{0,0,0},{0,0,0},{0,0,0},
    {0,0,0},{1,0,0},{2,3,0},{4,5,0},{6,0,0},{7,0,0},{0,0,0},
    {0,0,0},{2,0,0},{1,3,0},{4,6,0},{5,0,0},{7,0,0},{0,0,0},
    {0,0,0},{3,0,0},{1,2,0},{5,6,0},{4,0,0},{7,0,0},{0,0,0},
    {0,0,0},{1,2,0},{3,0,0},{4,0,0},{5,6,0},{7,0,0},{0,0,0},
    {0,0,0},{1,3,0},{2,0,0},{5,0,0},{4,6,0},{7,0,0},{0,0,0},
    {0,0,0},{2,3,0},{1,0,0},{6,0,0},{4,5,0},{7,0,0},{0,0,0},
    {0,0,0},{1,2,3},{4,5,6},{7,0,0},{0,0,0},{0,0,0},{0,0,0}};
__device__ constexpr int c_SSG[56][3] = {   // 1 = +, 0 = -
    {1,1,1},{1,1,1},{0,0,0},{0,1,1},{1,1,1},{1,1,1},{1,1,1},
    {1,1,1},{1,1,1},{0,0,1},{1,1,1},{0,1,1},{0,1,1},{1,1,1},
    {1,1,1},{1,1,1},{1,0,1},{0,1,1},{1,1,1},{1,1,1},{1,1,1},
    {1,1,1},{1,1,1},{1,1,1},{0,0,1},{0,1,1},{0,1,1},{1,1,1},
    {1,1,1},{1,0,1},{1,1,1},{1,1,1},{0,1,1},{1,1,1},{1,1,1},
    {1,1,1},{1,0,1},{0,1,1},{1,1,1},{1,0,1},{0,1,1},{1,1,1},
    {1,1,1},{1,0,1},{1,1,1},{1,1,1},{0,1,1},{1,1,1},{1,1,1},
    {1,1,1},{1,0,1},{1,0,1},{1,1,1},{1,1,1},{1,1,1},{1,1,1}};

// ---------------- helpers ---------------------------------------------------
__device__ __forceinline__ uint32_t smem_u32(const void* p) {
    uint32_t a;
    asm("{ .reg .u64 t; cvta.to.shared.u64 t, %1; cvt.u32.u64 %0, t; }" : "=r"(a) : "l"(p));
    return a;
}
#define SWZ(o) ((o) ^ (((o) >> 3) & 0x70))

__device__ __forceinline__ void ldm4(uint32_t* r, uint32_t addr) {
    asm volatile("ldmatrix.sync.aligned.m8n8.x4.shared.b16 {%0,%1,%2,%3}, [%4];"
        : "=r"(r[0]), "=r"(r[1]), "=r"(r[2]), "=r"(r[3]) : "r"(addr));
}
__device__ __forceinline__ void mma_f16(float* c, const uint32_t* a, uint32_t b0, uint32_t b1) {
    asm volatile(
        "mma.sync.aligned.m16n8k16.row.col.f32.f16.f16.f32 "
        "{%0,%1,%2,%3}, {%4,%5,%6,%7}, {%8,%9}, {%0,%1,%2,%3};"
        : "+f"(c[0]), "+f"(c[1]), "+f"(c[2]), "+f"(c[3])
        : "r"(a[0]), "r"(a[1]), "r"(a[2]), "r"(a[3]), "r"(b0), "r"(b1));
}
__device__ __forceinline__ void cp16(uint32_t d, const void* g) {
    asm volatile("cp.async.cg.shared.global [%0], [%1], 16;" :: "r"(d), "l"(g));
}
#define CP_COMMIT() asm volatile("cp.async.commit_group;")
#define CP_WAIT1()  asm volatile("cp.async.wait_group 1;")
#define CP_WAIT0()  asm volatile("cp.async.wait_group 0;")

// ============================================================================
// splitX: x[b,n,8] -> g_xf planes [i][b][n] (fp16)
// ============================================================================
__global__ __launch_bounds__(256)
void k_splitX(const float* __restrict__ x)
{
    size_t idx = blockIdx.x * 256 + threadIdx.x;    // (b,n)
    float x8[8];
    *(float4*)(x8)     = *(const float4*)(x + idx * 8);
    *(float4*)(x8 + 4) = *(const float4*)(x + idx * 8 + 4);
#pragma unroll
    for (int i = 0; i < 8; ++i)
        g_xf[(size_t)i * BN + idx] = __float2half(x8[i]);
}

// ============================================================================
// prepW (fused splitW + buildB), 2 n's per thread, half2 stores.
//   g_wrf[g][m][n] = fp16(w_right[m,n,g])
//   g_B[bj][m][s*512+n]: path>=0 -> weight[m,n,path]; -1 -> w_left[m,n,G[bj]];
//                        -2 -> 0 (padding)
// ============================================================================
__global__ __launch_bounds__(256)
void k_prepW(const float* __restrict__ weight, const float* __restrict__ w_left,
             const float* __restrict__ w_right)
{
    size_t idx2 = blockIdx.x * 256 + threadIdx.x;   // (m, n2)
    int m = (int)(idx2 >> 8), n = (int)(idx2 & 255) * 2;
    size_t bn0 = (size_t)m * 512 + n;
    float w[2][20], wl[2][4], wr[2][4];
#pragma unroll
    for (int j = 0; j < 2; ++j) {
#pragma unroll
        for (int q = 0; q < 5; ++q)
            *(float4*)(w[j] + q * 4) = *(const float4*)(weight + (bn0 + j) * 20 + q * 4);
        *(float4*)(wl[j]) = *(const float4*)(w_left + (bn0 + j) * 4);
        *(float4*)(wr[j]) = *(const float4*)(w_right + (bn0 + j) * 4);
    }

#pragma unroll
    for (int g = 0; g < 4; ++g)
        *(__half2*)(g_wrf + (size_t)g * N_IN * N_IN + bn0) =
            __floats2half2_rn(wr[0][g], wr[1][g]);

#pragma unroll
    for (int bj = 0; bj < 8; ++bj) {
        size_t base = ((size_t)bj * N_OUT + m) * KU + n;
#pragma unroll
        for (int s = 0; s < NSL; ++s) {
            const int p = c_SPATH[bj * NSL + s];
            float v0, v1;
            if (p >= 0)       { v0 = w[0][p];          v1 = w[1][p]; }
            else if (p == -1) { v0 = wl[0][c_G[bj]];   v1 = wl[1][c_G[bj]]; }
            else              { v0 = 0.f;              v1 = 0.f; }
            *(__half2*)(g_B + base + (size_t)s * 512) = __floats2half2_rn(v0, v1);
        }
    }
}

// ============================================================================
// Shared GEMM core: 128 x 128 CTA tile, 4 warps of 64x64, BK=64,
// 3-stage cp.async pipeline, single __syncthreads per k-iter, 128 threads.
// smem: 3 stages x (A 16KB + B 16KB) = 96KB dynamic.
// ============================================================================
struct GemmCtx {
    uint32_t smb;
    int lane, warp_m, warp_n;
    int ldrow, ldc16;
    uint32_t ld_sw;
    uint32_t a_lin, a_sw, a_kl;
    uint32_t b_lin, b_sw, b_kl;
    __device__ __forceinline__ void init(int tid) {
        lane = tid & 31;
        int wid = tid >> 5;
        warp_m = wid >> 1; warp_n = wid & 1;
        ldrow = tid >> 3; ldc16 = tid & 7;
        ld_sw = SWZ((uint32_t)(ldrow * 128 + ldc16 * 16));
        int a_r = warp_m * 64 + (lane & 7) + ((lane >> 3) & 1) * 8;
        a_lin = a_r * 128; a_sw = (a_r & 7) << 4; a_kl = (lane >> 4) * 16;
        int b_r = warp_n * 64 + (lane & 7) + (lane >> 4) * 8;
        b_lin = b_r * 128; b_sw = (b_r & 7) << 4; b_kl = ((lane >> 3) & 1) * 16;
    }
};

template <int LDK>
__device__ __forceinline__ void gemm_load(const GemmCtx& g, int s,
                                          const __half* Ap, size_t a_row0,
                                          const __half* Bp, size_t b_row0,
                                          int kk) {
    const uint32_t sA = g.smb + (uint32_t)s * 32768u;
    const uint32_t sB = sA + 16384u;
#pragma unroll
    for (int j = 0; j < 8; ++j) {
        int row = g.ldrow + j * 16;
        cp16(sA + g.ld_sw + j * 2048u, Ap + a_row0 + (size_t)row * LDK + kk * 64 + g.ldc16 * 8);
        cp16(sB + g.ld_sw + j * 2048u, Bp + b_row0 + (size_t)row * LDK + kk * 64 + g.ldc16 * 8);
    }
    CP_COMMIT();
}

__device__ __forceinline__ void gemm_compute(const GemmCtx& g, int s, float c[4][8][4]) {
    const uint32_t sA = g.smb + (uint32_t)s * 32768u;
    const uint32_t sB = sA + 16384u;
#pragma unroll
    for (int k16 = 0; k16 < 4; ++k16) {
        uint32_t af[4][4], bf[4][4];
#pragma unroll
        for (int mi = 0; mi < 4; ++mi)
            ldm4(af[mi], sA + g.a_lin + mi * 2048u + ((k16 * 32u + g.a_kl) ^ g.a_sw));
#pragma unroll
        for (int nj = 0; nj < 4; ++nj)
            ldm4(bf[nj], sB + g.b_lin + nj * 2048u + ((k16 * 32u + g.b_kl) ^ g.b_sw));
#pragma unroll
        for (int mi = 0; mi < 4; ++mi)
#pragma unroll
            for (int nj = 0; nj < 4; ++nj) {
                mma_f16(c[mi][nj * 2 + 0], af[mi], bf[nj][0], bf[nj][1]);
                mma_f16(c[mi][nj * 2 + 1], af[mi], bf[nj][2], bf[nj][3]);
            }
    }
}

__device__ __forceinline__ void gemm_store(const GemmCtx& g, float c[4][8][4],
                                           float* base, int b0, int n0, int ldn) {
    const int mrow = b0 + g.warp_m * 64 + (g.lane >> 2);
    const int ncol = n0 + g.warp_n * 64 + (g.lane & 3) * 2;
#pragma unroll
    for (int mi = 0; mi < 4; ++mi)
#pragma unroll
        for (int n8 = 0; n8 < 8; ++n8) {
            float* p0 = base + (size_t)(mrow + mi * 16) * ldn + ncol + n8 * 8;
            float* p1 = base + (size_t)(mrow + mi * 16 + 8) * ldn + ncol + n8 * 8;
            *(float2*)p0 = make_float2(c[mi][n8][0], c[mi][n8][1]);
            *(float2*)p1 = make_float2(c[mi][n8][2], c[mi][n8][3]);
        }
}

// ============================================================================
// xr GEMM (tensor, single fp16): g_outT[i][b][m] = sum_n x[b,n,i]*w_right[m,n,G[i]]
// grid (4, 16, 8), 128 threads.
// ============================================================================
__global__ __launch_bounds__(128)
void k_gemm_xr()
{
    extern __shared__ char sm[];
    GemmCtx g; g.smb = smem_u32(sm); g.init(threadIdx.x);
    const int n0 = blockIdx.x * 128, b0 = blockIdx.y * 128;
    const int ib = blockIdx.z, gg = c_G[ib];

    const size_t a_row0 = ((size_t)ib * B_DIM + b0) * N_IN;
    const size_t b_row0 = ((size_t)gg * N_IN + n0) * N_IN;

    float c[4][8][4];
#pragma unroll
    for (int mi = 0; mi < 4; ++mi)
#pragma unroll
        for (int nn = 0; nn < 8; ++nn)
#pragma unroll
            for (int q = 0; q < 4; ++q) c[mi][nn][q] = 0.f;

    gemm_load<N_IN>(g, 0, g_xf, a_row0, g_wrf, b_row0, 0);
    gemm_load<N_IN>(g, 1, g_xf, a_row0, g_wrf, b_row0, 1);
#pragma unroll 1
    for (int kt = 0; kt < NKT_XR; ++kt) {
        if (kt + 1 < NKT_XR) CP_WAIT1(); else CP_WAIT0();
        __syncthreads();
        if (kt + 2 < NKT_XR)
            gemm_load<N_IN>(g, (kt + 2) % 3, g_xf, a_row0, g_wrf, b_row0, kt + 2);
        gemm_compute(g, kt % 3, c);
    }

    gemm_store(g, c, g_outT + (size_t)ib * B_DIM * N_IN, b0, n0, N_IN);
}

// ============================================================================
// buildA fused with normalization, uniform 7-slice layout, 2 n's per thread:
//   read raw xr planes g_outT[i][b][n], normalize, combine with fp16 x planes,
//   pre-sum path groups in fp32, emit A (fp16); zero-pad slices for bj 0,7.
// ============================================================================
__global__ __launch_bounds__(256)
void k_buildA(const float* __restrict__ norm_a)
{
    size_t idx2 = blockIdx.x * 256 + threadIdx.x;   // (b, n2)
    int b = (int)(idx2 >> 8), n = (int)(idx2 & 255) * 2;
    size_t bn0 = (size_t)b * 512 + n;

    float r8[2][8];
#pragma unroll
    for (int i = 0; i < 8; ++i) {
        float2 v = *(const float2*)(g_outT + (size_t)i * BN + bn0);
        r8[0][i] = v.x; r8[1][i] = v.y;
    }

#pragma unroll
    for (int j = 0; j < 2; ++j) {
        float* r = r8[j];
        float n0 = fabsf(r[0]);
        float n1 = sqrtf(r[1]*r[1] + r[2]*r[2] + r[3]*r[3]);
        float n2 = sqrtf(r[4]*r[4] + r[5]*r[5] + r[6]*r[6]);
        float n3 = fabsf(r[7]);
        float4 na = *(const float4*)(norm_a + (n + j) * 4);
        float s0 = 1.f / (1.f + expf(-na.x));
        float s1 = 1.f / (1.f + expf(-na.y));
        float s2 = 1.f / (1.f + expf(-na.z));
        float s3 = 1.f / (1.f + expf(-na.w));
        float d0 = 1.f / (s0 * (n0 - 1.f) + 1.f + 1e-6f);
        float d1 = 1.f / (s1 * (n1 - 1.f) + 1.f + 1e-6f);
        float d2 = 1.f / (s2 * (n2 - 1.f) + 1.f + 1e-6f);
        float d3 = 1.f / (s3 * (n3 - 1.f) + 1.f + 1e-6f);
        r[0] *= d0; r[1] *= d1; r[2] *= d1; r[3] *= d1;
        r[4] *= d2; r[5] *= d2; r[6] *= d2; r[7] *= d3;
    }

    float x8[2][8];
#pragma unroll
    for (int i = 0; i < 8; ++i) {
        __half2 xv = *(const __half2*)(g_xf + (size_t)i * BN + bn0);
        float2 xf = __half22float2(xv);
        x8[0][i] = xf.x; x8[1][i] = xf.y;
    }

#pragma unroll
    for (int bj = 0; bj < 8; ++bj) {
        size_t base = ((size_t)bj * B_DIM + b) * KU + n;
#pragma unroll
        for (int s = 0; s < NSL; ++s) {
            const int si = bj * NSL + s;
            const int nt = c_SNT[si];
            float v0 = 0.f, v1 = 0.f;
            if (nt == 0) {              // left-linear slice
                v0 = x8[0][bj]; v1 = x8[1][bj];
            } else if (nt > 0) {
#pragma unroll
                for (int q = 0; q < 3; ++q) {
                    if (q >= nt) break;
                    const int t = c_ST[si][q];
                    const int bk = c_MS[c_MS[t] ^ c_MS[bj]];
                    if (c_SSG[si][q]) {
                        v0 += x8[0][t] * r8[0][bk];
                        v1 += x8[1][t] * r8[1][bk];
                    } else {
                        v0 -= x8[0][t] * r8[0][bk];
                        v1 -= x8[1][t] * r8[1][bk];
                    }
                }
            } // nt == -1: padding, leave zeros
            *(__half2*)(g_A + base + (size_t)s * 512) = __floats2half2_rn(v0, v1);
        }
    }
}

// ============================================================================
// main GEMM (tensor, fp16, uniform K=3584): g_outT[bj][b][m] = sum_k A[b,k]*B[m,k]
// grid (4, 16, 8), 128 threads, NKT=56.
// ============================================================================
__global__ __launch_bounds__(128)
void k_gemm()
{
    extern __shared__ char sm[];
    GemmCtx g; g.smb = smem_u32(sm); g.init(threadIdx.x);
    const int n0 = blockIdx.x * 128, b0 = blockIdx.y * 128;
    const int bj = blockIdx.z;

    const size_t a_row0 = ((size_t)bj * B_DIM + b0) * KU;
    const size_t b_row0 = ((size_t)bj * N_OUT + n0) * KU;

    float c[4][8][4];
#pragma unroll
    for (int mi = 0; mi < 4; ++mi)
#pragma unroll
        for (int nn = 0; nn < 8; ++nn)
#pragma unroll
            for (int q = 0; q < 4; ++q) c[mi][nn][q] = 0.f;

    gemm_load<KU>(g, 0, g_A, a_row0, g_B, b_row0, 0);
    gemm_load<KU>(g, 1, g_A, a_row0, g_B, b_row0, 1);
#pragma unroll 1
    for (int kt = 0; kt < NKT; ++kt) {
        if (kt + 1 < NKT) CP_WAIT1(); else CP_WAIT0();
        __syncthreads();
        if (kt + 2 < NKT)
            gemm_load<KU>(g, (kt + 2) % 3, g_A, a_row0, g_B, b_row0, kt + 2);
        gemm_compute(g, kt % 3, c);
    }

    gemm_store(g, c, g_outT + (size_t)bj * B_DIM * N_OUT, b0, n0, N_OUT);
}

// ============================================================================
// merge: out[b][m][bj] = (g_outT[bj][b][m] + (bj==0)*b_left[m]) * RSQRT2
// ============================================================================
__global__ __launch_bounds__(256)
void k_merge(const float* __restrict__ b_left, float* __restrict__ out)
{
    size_t idx = blockIdx.x * 256 + threadIdx.x;
    int m = (int)(idx & 511);
    float v[8];
#pragma unroll
    for (int bj = 0; bj < 8; ++bj)
        v[bj] = g_outT[(size_t)bj * B_DIM * N_OUT + idx];
    v[0] += b_left[m];
    float* dst = out + idx * 8;
    *(float4*)(dst)     = make_float4(v[0]*RSQRT2, v[1]*RSQRT2, v[2]*RSQRT2, v[3]*RSQRT2);
    *(float4*)(dst + 4) = make_float4(v[4]*RSQRT2, v[5]*RSQRT2, v[6]*RSQRT2, v[7]*RSQRT2);
}

// ============================================================================
extern "C" void kernel_launch(void* const* d_in, const int* in_sizes, int n_in,
                              void* d_out, int out_size) {
    const float* x       = (const float*)d_in[0];
    const float* weight  = (const float*)d_in[1];
    const float* w_right = (const float*)d_in[2];
    const float* w_left  = (const float*)d_in[3];
    const float* b_left  = (const float*)d_in[4];
    const float* norm_a  = (const float*)d_in[5];
    float* out = (float*)d_out;

    cudaFuncSetAttribute(k_gemm,    cudaFuncAttributeMaxDynamicSharedMemorySize, 98304);
    cudaFuncSetAttribute(k_gemm_xr, cudaFuncAttributeMaxDynamicSharedMemorySize, 98304);

    k_splitX<<<(int)(BN / 256), 256>>>(x);
    k_prepW<<<(N_OUT * N_IN / 2) / 256, 256>>>(weight, w_left, w_right);
    dim3 gx(N_IN / 128, B_DIM / 128, 8);
    k_gemm_xr<<<gx, 128, 98304>>>();
    k_buildA<<<(int)(BN / 2 / 256), 256>>>(norm_a);
    dim3 gg(N_OUT / 128, B_DIM / 128, 8);
    k_gemm<<<gg, 128, 98304>>>();
    k_merge<<<(B_DIM * N_OUT) / 256, 256>>>(b_left, out);
}